// round 7
// baseline (speedup 1.0000x reference)
#include <cuda_runtime.h>

// GridMask: out = x * mask(n,s,h,w), broadcast over C.
// x: [N=8, C=3, S=16, H=512, W=512] fp32
// d: [N] int32, st_h/st_w: [N, S] int32
// mask = ((h + OFF_H - st_h) mod d < l) || ((w + OFF_W - st_w) mod d < l),
// l = ceil(d/2), OFF_H = OFF_W = 106 (HH = ceil(512*sqrt(2)) = 725).
//
// Byte-reduction: where mask==0 the output is exactly 0 and x is not read
// (~24% of read traffic skipped).
// Persistent grid-stride form: 148*16 resident CTAs loop over rows, removing
// ~28 wave transitions and keeping per-SM load depth continuous.

#define GN 8
#define GC 3
#define GS 16
#define GH 512
#define GW 512
#define OFF_H 106
#define OFF_W 106
#define NROWS (GN * GS * GH)       // 65536 (n,s,h) rows
#define NBLOCKS 2368               // 148 SMs * 16 resident CTAs

__global__ __launch_bounds__(128, 16)
void gridmask_kernel(const float* __restrict__ x,
                     const int* __restrict__ d,
                     const int* __restrict__ st_h,
                     const int* __restrict__ st_w,
                     float* __restrict__ out) {
    const int tid = threadIdx.x;
    const int w   = tid << 2;                    // 0,4,...,508
    const size_t cstride = (size_t)GS * GH * GW; // 4194304

    for (int bid = blockIdx.x; bid < NROWS; bid += NBLOCKS) {
        // bid encodes (n, s, h): bid = ((n*GS + s) << 9) | h
        const int h  = bid & (GH - 1);
        const int ns = bid >> 9;
        const int s  = ns & (GS - 1);
        const int n  = ns >> 4;

        const int dn = d[n];
        const int l  = (dn + 1) >> 1;            // ceil(d * 0.5)
        const int sh = st_h[n * GS + s] % dn;
        const int sw = st_w[n * GS + s] % dn;

        // h + OFF_H - sh + dn >= 107 > 0 -> single unsigned mod ok
        const bool row_hit =
            ((unsigned)(h + OFF_H - sh + dn) % (unsigned)dn) < (unsigned)l;

        // Single mod for lane 0; lanes 1..3 via incremental wrap.
        const unsigned ud = (unsigned)dn;
        const unsigned ul = (unsigned)l;
        unsigned r0 = (unsigned)(w + OFF_W - sw + dn) % ud;
        unsigned r1 = r0 + 1u; if (r1 >= ud) r1 -= ud;
        unsigned r2 = r0 + 2u; if (r2 >= ud) r2 -= ud;
        unsigned r3 = r0 + 3u; if (r3 >= ud) r3 -= ud;

        const bool c0 = r0 < ul;
        const bool c1 = r1 < ul;
        const bool c2 = r2 < ul;
        const bool c3 = r3 < ul;
        const bool any = row_hit | c0 | c1 | c2 | c3;

        // layout: idx = (((n*C + c)*S + s)*H + h)*W + w
        const size_t base0 = (((size_t)n * GC) * GS + (size_t)s)
                           * ((size_t)GH * GW)
                           + (size_t)h * GW + (size_t)w;

        float4 v0 = make_float4(0.f, 0.f, 0.f, 0.f);
        float4 v1 = v0;
        float4 v2 = v0;

        if (any) {
            v0 = __ldcs(reinterpret_cast<const float4*>(x + base0));
            v1 = __ldcs(reinterpret_cast<const float4*>(x + base0 + cstride));
            v2 = __ldcs(reinterpret_cast<const float4*>(x + base0 + 2 * cstride));

            const float m0 = (row_hit | c0) ? 1.0f : 0.0f;
            const float m1 = (row_hit | c1) ? 1.0f : 0.0f;
            const float m2 = (row_hit | c2) ? 1.0f : 0.0f;
            const float m3 = (row_hit | c3) ? 1.0f : 0.0f;

            v0.x *= m0; v0.y *= m1; v0.z *= m2; v0.w *= m3;
            v1.x *= m0; v1.y *= m1; v1.z *= m2; v1.w *= m3;
            v2.x *= m0; v2.y *= m1; v2.z *= m2; v2.w *= m3;
        }

        __stcs(reinterpret_cast<float4*>(out + base0),               v0);
        __stcs(reinterpret_cast<float4*>(out + base0 + cstride),     v1);
        __stcs(reinterpret_cast<float4*>(out + base0 + 2 * cstride), v2);
    }
}

extern "C" void kernel_launch(void* const* d_in, const int* in_sizes, int n_in,
                              void* d_out, int out_size) {
    const float* x   = (const float*)d_in[0];
    const int* d     = (const int*)d_in[1];
    const int* st_h  = (const int*)d_in[2];
    const int* st_w  = (const int*)d_in[3];
    float* out       = (float*)d_out;

    gridmask_kernel<<<NBLOCKS, 128>>>(x, d, st_h, st_w, out);
}

// round 8
// speedup vs baseline: 1.1830x; 1.1830x over previous
#include <cuda_runtime.h>

// GridMask: out = x * mask(n,s,h,w), broadcast over C.
// x: [N=8, C=3, S=16, H=512, W=512] fp32
// d: [N] int32, st_h/st_w: [N, S] int32
// mask = ((h + OFF_H - st_h) mod d < l) || ((w + OFF_W - st_w) mod d < l),
// l = ceil(d/2), OFF_H = OFF_W = 106 (HH = ceil(512*sqrt(2)) = 725).
//
// Final form (Round-4 winner, roofline-complete):
//  - one CTA per (n,s,h) row, 128 threads x float4, fully coalesced
//  - mask==0 spans skip the x read entirely (~24% of read traffic removed;
//    zero runs are 192-448B >> 32B sectors, so predicated LDGs drop sectors)
//  - straight-line body, 16 CTAs/SM resident -> inter-row MLP comes from
//    CTA-level parallelism (persistent-loop variant measured 18% slower)

#define GN 8
#define GC 3
#define GS 16
#define GH 512
#define GW 512
#define OFF_H 106
#define OFF_W 106

__global__ __launch_bounds__(128, 16)
void gridmask_kernel(const float* __restrict__ x,
                     const int* __restrict__ d,
                     const int* __restrict__ st_h,
                     const int* __restrict__ st_w,
                     float* __restrict__ out) {
    // blockIdx.x encodes (n, s, h): bid = ((n*GS + s) << 9) | h
    const int bid = blockIdx.x;
    const int h  = bid & (GH - 1);
    const int ns = bid >> 9;
    const int s  = ns & (GS - 1);
    const int n  = ns >> 4;

    const int dn = d[n];
    const int l  = (dn + 1) >> 1;                 // ceil(d * 0.5)
    const int sh = st_h[n * GS + s] % dn;
    const int sw = st_w[n * GS + s] % dn;

    // h + OFF_H - sh + dn >= 107 > 0  -> single unsigned mod ok
    const bool row_hit =
        ((unsigned)(h + OFF_H - sh + dn) % (unsigned)dn) < (unsigned)l;

    const int w = threadIdx.x << 2;               // 0,4,...,508

    // per-lane column hits
    const unsigned ud = (unsigned)dn;
    const unsigned ul = (unsigned)l;
    const unsigned cb = (unsigned)(w + OFF_W - sw + dn);
    const bool c0 = ((cb + 0u) % ud) < ul;
    const bool c1 = ((cb + 1u) % ud) < ul;
    const bool c2 = ((cb + 2u) % ud) < ul;
    const bool c3 = ((cb + 3u) % ud) < ul;

    const bool any = row_hit | c0 | c1 | c2 | c3;

    const float m0 = (row_hit | c0) ? 1.0f : 0.0f;
    const float m1 = (row_hit | c1) ? 1.0f : 0.0f;
    const float m2 = (row_hit | c2) ? 1.0f : 0.0f;
    const float m3 = (row_hit | c3) ? 1.0f : 0.0f;

    // layout: idx = (((n*C + c)*S + s)*H + h)*W + w ; channel stride = S*H*W
    const size_t cstride = (size_t)GS * GH * GW;  // 4194304
    const size_t base0 = (((size_t)n * GC) * GS + (size_t)s) * ((size_t)GH * GW)
                       + (size_t)h * GW + (size_t)w;

    const float4* p0 = reinterpret_cast<const float4*>(x + base0);
    const float4* p1 = reinterpret_cast<const float4*>(x + base0 + cstride);
    const float4* p2 = reinterpret_cast<const float4*>(x + base0 + 2 * cstride);

    float4 v0 = make_float4(0.f, 0.f, 0.f, 0.f);
    float4 v1 = v0;
    float4 v2 = v0;

    // Skip the reads entirely when all 4 mask lanes are zero (output is 0).
    if (any) {
        v0 = __ldcs(p0);
        v1 = __ldcs(p1);
        v2 = __ldcs(p2);

        v0.x *= m0; v0.y *= m1; v0.z *= m2; v0.w *= m3;
        v1.x *= m0; v1.y *= m1; v1.z *= m2; v1.w *= m3;
        v2.x *= m0; v2.y *= m1; v2.z *= m2; v2.w *= m3;
    }

    __stcs(reinterpret_cast<float4*>(out + base0),                v0);
    __stcs(reinterpret_cast<float4*>(out + base0 + cstride),      v1);
    __stcs(reinterpret_cast<float4*>(out + base0 + 2 * cstride),  v2);
}

extern "C" void kernel_launch(void* const* d_in, const int* in_sizes, int n_in,
                              void* d_out, int out_size) {
    const float* x   = (const float*)d_in[0];
    const int* d     = (const int*)d_in[1];
    const int* st_h  = (const int*)d_in[2];
    const int* st_w  = (const int*)d_in[3];
    float* out       = (float*)d_out;

    // one block per (n, s, h) row: 8*16*512 = 65536 blocks, 128 threads each
    gridmask_kernel<<<GN * GS * GH, 128>>>(x, d, st_h, st_w, out);
}